// round 13
// baseline (speedup 1.0000x reference)
#include <cuda_runtime.h>
#include <cstdint>

// Problem constants
#define TT 512
#define BB 128
#define HH 1024
#define SIGMA_REC 0.15811388300841897f   // sqrt(2/0.2)*0.05

// Grid / threads
#define NCTA 128          // 4 row-blocks x 32 col-blocks
#define NTHREADS 512      // 8 k-split groups x 64 threads
#define NGROUP 8
#define CK 64             // k per staged chunk
#define NCHUNK (HH / CK)  // 16
#define PAIRS_PER_CHUNK 32
#define PAIRS_PER_GROUP 4 // pairs per group per chunk

// SMEM layout (floats)
#define ASTRIDE 68                   // 64 k + 4 pad: conflict-free & 16B-aligned rows
#define ABUF (32 * ASTRIDE)          // 2176
#define W_FLOATS (HH * 32)           // 32768, k-pair-interleaved: idx=(k>>1)*64 + c*2 + (k&1)
#define A_OFF W_FLOATS
#define SCR_OFF (A_OFF + 2 * ABUF)   // 37120
#define SCR_STRIDE 20                // 16 floats + 4 pad per thread-slot
#define SCR_GROUP (64 * SCR_STRIDE)  // 1280
#define WIH_OFF (SCR_OFF + 7 * SCR_GROUP)   // 46080
#define BIAS_OFF (WIH_OFF + 64)
#define SMEM_FLOATS (BIAS_OFF + 32)         // 46176
#define SMEM_BYTES (SMEM_FLOATS * 4)        // 184704 B (< 227 KB)

#define FMA2(acc, a, w) asm("fma.rn.f32x2 %0, %1, %2, %0;" : "+l"(acc) : "l"(a), "l"(w))

// Per-CTA progress flag: value v means out[0..v-1] tiles from this producer are
// globally visible. Monotonic within a launch; zeroed by init kernel per launch
// (init kernel is part of the captured graph -> reset on every replay).
__device__ unsigned g_pflags[NCTA];

__global__ void rnn_init_kernel() {
    if (threadIdx.x < NCTA) g_pflags[threadIdx.x] = 0u;
}

__device__ __forceinline__ void st_rel(unsigned* p, unsigned v) {
    asm volatile("st.global.release.gpu.u32 [%0], %1;" :: "l"(p), "r"(v) : "memory");
}
__device__ __forceinline__ unsigned ld_acq(const unsigned* p) {
    unsigned v;
    asm volatile("ld.global.acquire.gpu.u32 %0, [%1];" : "=r"(v) : "l"(p) : "memory");
    return v;
}
// Fast path: single acquire load (steady state: already satisfied).
// Miss path: backoff spin so 127 pollers don't hammer one L2 line.
__device__ __forceinline__ void wait_flag(const unsigned* p, unsigned target) {
    if (ld_acq(p) >= target) return;
    while (ld_acq(p) < target) { __nanosleep(64); }
}

__global__ void __launch_bounds__(NTHREADS, 1)
rnn_persistent_kernel(const float* __restrict__ inp,
                      const float* __restrict__ init_state,
                      const float* __restrict__ noise,
                      const float* __restrict__ wih,
                      const float* __restrict__ whh,
                      const float* __restrict__ bias,
                      float* __restrict__ out)
{
    extern __shared__ float sm[];
    float* sW    = sm;              // [512 j][32 c][2 parity]  W_hh k-pair-interleaved
    float* sA    = sm + A_OFF;      // [2][32 r][68]  relu(state), plain (no dup)
    float* sScr  = sm + SCR_OFF;    // [7 g][64 s][20] partial tiles
    float* sWih  = sm + WIH_OFF;    // [2][32]
    float* sBias = sm + BIAS_OFF;   // [32]

    const int tid  = threadIdx.x;
    const int cta  = blockIdx.x;
    const int row0 = (cta >> 5) * 32;   // batch-row block
    const int col0 = (cta & 31) * 32;   // hidden-col block
    const unsigned* rowFlags = &g_pflags[(cta >> 5) * 32];  // 32 producers of my rows

    // One-time: stage W strip k-pair-interleaved
    for (int idx = tid; idx < W_FLOATS; idx += NTHREADS) {
        const int k = idx >> 5, c = idx & 31;
        sW[(k >> 1) * 64 + c * 2 + (k & 1)] = whh[k * HH + col0 + c];
    }
    if (tid < 32) {
        sWih[tid]      = wih[col0 + tid];
        sWih[32 + tid] = wih[HH + col0 + tid];
        sBias[tid]     = bias[col0 + tid];
    }

    // K-split groups: group g handles pairs [g*4, g*4+4) of every 32-pair chunk.
    const int group = tid >> 6;         // 0..7
    const int s     = tid & 63;
    const int cql   = s >> 3;           // 0..7 -> cols cql*4 .. +3
    const int rql   = s & 7;            // rows {rql, rql+8, rql+16, rql+24}
    const int clo   = cql * 4;

    // Staging mapping: 512 threads store one relu'd float4 (32 rows x 16 quads)
    const int l_r = tid >> 4;           // 0..31
    const int l_q = tid & 15;           // 0..15

    // out[0] = initial_state (own tile), then publish flag=1
    if (tid < 256) {
        const int r = tid >> 3, c4 = (tid & 7) * 4;
        const float4 v = *(const float4*)&init_state[(row0 + r) * HH + col0 + c4];
        *(float4*)&out[(row0 + r) * HH + col0 + c4] = v;
    }
    __syncthreads();
    if (tid == 0) st_rel(&g_pflags[cta], 1u);

    #pragma unroll 1
    for (int t = 0; t < TT; ++t) {
        const float* Ot = out + (size_t)t * (BB * HH);
        float*       On = out + (size_t)(t + 1) * (BB * HH);
        const unsigned need = (unsigned)(t + 1);   // flag value that makes out[t] visible

        // Wait for chunk-0 producers (cols 0..63 -> cbs 0,1), then stage chunk 0.
        if (tid == 0) { wait_flag(&rowFlags[0], need); wait_flag(&rowFlags[1], need); }
        __syncthreads();
        {
            float4 v = *(const float4*)&Ot[(row0 + l_r) * HH + l_q * 4];
            v.x = fmaxf(v.x, 0.f); v.y = fmaxf(v.y, 0.f); v.z = fmaxf(v.z, 0.f); v.w = fmaxf(v.w, 0.f);
            *(float4*)&sA[l_r * ASTRIDE + l_q * 4] = v;
        }
        // Poll chunk-1 producers while the staging stores drain.
        if (tid == 0) { wait_flag(&rowFlags[2], need); wait_flag(&rowFlags[3], need); }
        __syncthreads();

        unsigned long long acc[4][4];
        #pragma unroll
        for (int i = 0; i < 4; ++i)
            #pragma unroll
            for (int j = 0; j < 4; ++j) acc[i][j] = 0ull;

        #pragma unroll 1
        for (int ck = 0; ck < NCHUNK; ++ck) {
            // Prefetch next chunk (its producers were verified one chunk-tail ago)
            float4 v;
            const int nb = (ck + 1) & 1;
            if (ck < NCHUNK - 1) {
                v = *(const float4*)&Ot[(row0 + l_r) * HH + (ck + 1) * CK + l_q * 4];
            }

            const float* aB = &sA[(ck & 1) * ABUF];
            const int jloc  = group * PAIRS_PER_GROUP;           // pair idx within chunk
            const int jglob = ck * PAIRS_PER_CHUNK + jloc;       // global pair idx
            #pragma unroll
            for (int jj = 0; jj < PAIRS_PER_GROUP; ++jj) {
                const int jo2 = (jloc + jj) * 2;
                // a pairs (k even, k odd) for 4 strided rows — no duplication
                const unsigned long long a0 = *(const unsigned long long*)(aB + (rql +  0) * ASTRIDE + jo2);
                const unsigned long long a1 = *(const unsigned long long*)(aB + (rql +  8) * ASTRIDE + jo2);
                const unsigned long long a2 = *(const unsigned long long*)(aB + (rql + 16) * ASTRIDE + jo2);
                const unsigned long long a3 = *(const unsigned long long*)(aB + (rql + 24) * ASTRIDE + jo2);
                // W k-pairs for 4 cols
                const float* wj = sW + (size_t)(jglob + jj) * 64 + cql * 8;
                const ulonglong2 w01 = *(const ulonglong2*)(wj);
                const ulonglong2 w23 = *(const ulonglong2*)(wj + 4);
                FMA2(acc[0][0], a0, w01.x); FMA2(acc[0][1], a0, w01.y);
                FMA2(acc[0][2], a0, w23.x); FMA2(acc[0][3], a0, w23.y);
                FMA2(acc[1][0], a1, w01.x); FMA2(acc[1][1], a1, w01.y);
                FMA2(acc[1][2], a1, w23.x); FMA2(acc[1][3], a1, w23.y);
                FMA2(acc[2][0], a2, w01.x); FMA2(acc[2][1], a2, w01.y);
                FMA2(acc[2][2], a2, w23.x); FMA2(acc[2][3], a2, w23.y);
                FMA2(acc[3][0], a3, w01.x); FMA2(acc[3][1], a3, w01.y);
                FMA2(acc[3][2], a3, w23.x); FMA2(acc[3][3], a3, w23.y);
            }

            if (ck < NCHUNK - 1) {
                // Lookahead poll: producers of chunk ck+2 (cbs 2ck+4, 2ck+5).
                // In steady state these were satisfied long ago -> single LDG.
                if (ck < NCHUNK - 2 && tid == 0) {
                    wait_flag(&rowFlags[2 * ck + 4], need);
                    wait_flag(&rowFlags[2 * ck + 5], need);
                }
                v.x = fmaxf(v.x, 0.f); v.y = fmaxf(v.y, 0.f); v.z = fmaxf(v.z, 0.f); v.w = fmaxf(v.w, 0.f);
                *(float4*)&sA[nb * ABUF + l_r * ASTRIDE + l_q * 4] = v;
                __syncthreads();
            }
        }

        // Pair-sum: even-k + odd-k partials
        float c_[4][4];
        #pragma unroll
        for (int i = 0; i < 4; ++i)
            #pragma unroll
            for (int j = 0; j < 4; ++j) {
                unsigned lo, hi;
                asm("mov.b64 {%0, %1}, %2;" : "=r"(lo), "=r"(hi) : "l"(acc[i][j]));
                c_[i][j] = __uint_as_float(lo) + __uint_as_float(hi);
            }

        // Groups 1-7: store partial tiles. Group 0: prefetch epilogue operands.
        float4 old4[4], nz4[4]; float2 iv2[4];
        if (group != 0) {
            float* dst = &sScr[(group - 1) * SCR_GROUP + s * SCR_STRIDE];
            #pragma unroll
            for (int i = 0; i < 4; ++i)
                *(float4*)(dst + i * 4) = make_float4(c_[i][0], c_[i][1], c_[i][2], c_[i][3]);
        } else {
            #pragma unroll
            for (int i = 0; i < 4; ++i) {
                const int gr = row0 + rql + 8 * i;
                old4[i] = *(const float4*)&Ot[gr * HH + col0 + clo];   // own tile: always visible
                nz4[i]  = *(const float4*)&noise[((size_t)t * BB + gr) * HH + col0 + clo];
                iv2[i]  = *(const float2*)&inp[((size_t)t * BB + gr) * 2];
            }
        }
        __syncthreads();

        if (group == 0) {
            // Reduce the 7 partial tiles
            #pragma unroll 1
            for (int g = 1; g < NGROUP; ++g) {
                const float* src = &sScr[(g - 1) * SCR_GROUP + s * SCR_STRIDE];
                #pragma unroll
                for (int i = 0; i < 4; ++i) {
                    const float4 p = *(const float4*)(src + i * 4);
                    c_[i][0] += p.x; c_[i][1] += p.y; c_[i][2] += p.z; c_[i][3] += p.w;
                }
            }

            const float wa0 = sWih[clo],      wa1 = sWih[clo + 1],      wa2 = sWih[clo + 2],      wa3 = sWih[clo + 3];
            const float wb0 = sWih[32 + clo], wb1 = sWih[32 + clo + 1], wb2 = sWih[32 + clo + 2], wb3 = sWih[32 + clo + 3];
            const float b0  = sBias[clo],     b1  = sBias[clo + 1],     b2  = sBias[clo + 2],     b3  = sBias[clo + 3];

            #pragma unroll
            for (int i = 0; i < 4; ++i) {
                const int gr = row0 + rql + 8 * i;
                float4 res;
                res.x = 0.8f * old4[i].x + 0.2f * (c_[i][0] + iv2[i].x * wa0 + iv2[i].y * wb0 + b0 + SIGMA_REC * nz4[i].x);
                res.y = 0.8f * old4[i].y + 0.2f * (c_[i][1] + iv2[i].x * wa1 + iv2[i].y * wb1 + b1 + SIGMA_REC * nz4[i].y);
                res.z = 0.8f * old4[i].z + 0.2f * (c_[i][2] + iv2[i].x * wa2 + iv2[i].y * wb2 + b2 + SIGMA_REC * nz4[i].z);
                res.w = 0.8f * old4[i].w + 0.2f * (c_[i][3] + iv2[i].x * wa3 + iv2[i].y * wb3 + b3 + SIGMA_REC * nz4[i].w);
                *(float4*)&On[gr * HH + col0 + clo] = res;
            }
        }

        // Publish: all On tile stores happen-before the release flag
        // (group0 STGs -> __syncthreads -> thread0 release).
        __syncthreads();
        if (tid == 0) st_rel(&g_pflags[cta], (unsigned)(t + 2));
        // No grid barrier: next iteration's waits gate only on the producers
        // we actually read, two chunks ahead of use.
    }
}

extern "C" void kernel_launch(void* const* d_in, const int* in_sizes, int n_in,
                              void* d_out, int out_size) {
    const float* inp   = (const float*)d_in[0];  // [512,128,2]
    const float* inis  = (const float*)d_in[1];  // [128,1024]
    const float* noise = (const float*)d_in[2];  // [512,128,1024]
    const float* wih   = (const float*)d_in[3];  // [2,1024]
    const float* whh   = (const float*)d_in[4];  // [1024,1024]
    const float* bias  = (const float*)d_in[5];  // [1,1024]
    float* out = (float*)d_out;                  // [513,128,1024]

    cudaFuncSetAttribute(rnn_persistent_kernel,
                         cudaFuncAttributeMaxDynamicSharedMemorySize, SMEM_BYTES);

    rnn_init_kernel<<<1, 128>>>();
    rnn_persistent_kernel<<<NCTA, NTHREADS, SMEM_BYTES>>>(inp, inis, noise, wih, whh, bias, out);
}

// round 14
// speedup vs baseline: 1.0495x; 1.0495x over previous
#include <cuda_runtime.h>
#include <cstdint>

// Problem constants
#define TT 512
#define BB 128
#define HH 1024
#define SIGMA_REC 0.15811388300841897f   // sqrt(2/0.2)*0.05

// Grid / threads
#define NCTA 128          // 4 row-blocks x 32 col-blocks
#define NTHREADS 512      // 8 k-split groups x 64 threads
#define NGROUP 8
#define CK 128            // k per staged chunk (R14: doubled -> 8 chunks, 8 syncs)
#define NCHUNK (HH / CK)  // 8
#define PAIRS_PER_CHUNK 64
#define PAIRS_PER_GROUP 8 // pairs per group per chunk

// SMEM layout (floats)
#define ASTRIDE 132                  // 128 k + 4 pad: conflict-free & 16B-aligned rows
#define ABUF (32 * ASTRIDE)          // 4224
#define W_FLOATS (HH * 32)           // 32768, k-pair-interleaved: idx=(k>>1)*64 + c*2 + (k&1)
#define A_OFF W_FLOATS
#define SCR_OFF (A_OFF + 2 * ABUF)   // 41216
#define SCR_STRIDE 20                // 16 floats + 4 pad per thread-slot
#define SCR_GROUP (64 * SCR_STRIDE)  // 1280
#define EPI_OFF (SCR_OFF + 7 * SCR_GROUP)   // 50176: group0 per-thread epilogue slots
#define EPI_STRIDE 44                // old[16] nz[16] iv[8] + pad, 16B-aligned
#define WIH_OFF (EPI_OFF + 64 * EPI_STRIDE) // 52992
#define BIAS_OFF (WIH_OFF + 64)             // 53056
#define SMEM_FLOATS (BIAS_OFF + 32)         // 53088
#define SMEM_BYTES (SMEM_FLOATS * 4)        // 212352 B (< 227 KB)

#define FMA2(acc, a, w) asm("fma.rn.f32x2 %0, %1, %2, %0;" : "+l"(acc) : "l"(a), "l"(w))

__device__ unsigned g_flags[NCTA];

__global__ void rnn_init_kernel() {
    if (threadIdx.x < NCTA) g_flags[threadIdx.x] = 0u;
}

__device__ __forceinline__ void st_rel(unsigned* p, unsigned v) {
    asm volatile("st.global.release.gpu.u32 [%0], %1;" :: "l"(p), "r"(v) : "memory");
}
__device__ __forceinline__ unsigned ld_acq(const unsigned* p) {
    unsigned v;
    asm volatile("ld.global.acquire.gpu.u32 %0, [%1];" : "=r"(v) : "l"(p) : "memory");
    return v;
}

// All-CTA barrier (fastest measured variant, R10): per-CTA release flag + all threads poll.
__device__ __forceinline__ void grid_barrier(unsigned epoch) {
    __syncthreads();
    if (threadIdx.x == 0) st_rel(&g_flags[blockIdx.x], epoch);
    const unsigned idx = threadIdx.x & (NCTA - 1);
    while (ld_acq(&g_flags[idx]) < epoch) { }
    __syncthreads();
}

__global__ void __launch_bounds__(NTHREADS, 1)
rnn_persistent_kernel(const float* __restrict__ inp,
                      const float* __restrict__ init_state,
                      const float* __restrict__ noise,
                      const float* __restrict__ wih,
                      const float* __restrict__ whh,
                      const float* __restrict__ bias,
                      float* __restrict__ out)
{
    extern __shared__ float sm[];
    float* sW    = sm;              // [512 j][32 c][2 parity]  W_hh k-pair-interleaved
    float* sA    = sm + A_OFF;      // [2][32 r][132]  relu(state)
    float* sScr  = sm + SCR_OFF;    // [7 g][64 s][20] partial tiles
    float* sEpi  = sm + EPI_OFF;    // [64 s][44] group0 private: old/nz/iv
    float* sWih  = sm + WIH_OFF;    // [2][32]
    float* sBias = sm + BIAS_OFF;   // [32]

    const int tid  = threadIdx.x;
    const int cta  = blockIdx.x;
    const int row0 = (cta >> 5) * 32;   // batch-row block
    const int col0 = (cta & 31) * 32;   // hidden-col block

    // One-time: stage W strip k-pair-interleaved
    for (int idx = tid; idx < W_FLOATS; idx += NTHREADS) {
        const int k = idx >> 5, c = idx & 31;
        sW[(k >> 1) * 64 + c * 2 + (k & 1)] = whh[k * HH + col0 + c];
    }
    if (tid < 32) {
        sWih[tid]      = wih[col0 + tid];
        sWih[32 + tid] = wih[HH + col0 + tid];
        sBias[tid]     = bias[col0 + tid];
    }

    // K-split groups: group g handles pairs [g*8, g*8+8) of every 64-pair chunk.
    const int group = tid >> 6;         // 0..7
    const int s     = tid & 63;
    const int cql   = s >> 3;           // 0..7 -> cols cql*4 .. +3
    const int rql   = s & 7;            // rows {rql, rql+8, rql+16, rql+24}
    const int clo   = cql * 4;

    // Staging mapping: each thread stores two relu'd float4 (32 rows x 32 quads)
    const int l_r = tid >> 4;           // 0..31
    const int l_q = tid & 15;           // quads l_q and l_q+16

    // out[0] = initial_state; group0 also seeds its SMEM old-state slots.
    if (tid < 256) {
        const int r = tid >> 3, c4 = (tid & 7) * 4;
        const float4 v = *(const float4*)&init_state[(row0 + r) * HH + col0 + c4];
        *(float4*)&out[(row0 + r) * HH + col0 + c4] = v;
    }
    if (group == 0) {
        float* ep = &sEpi[s * EPI_STRIDE];
        #pragma unroll
        for (int i = 0; i < 4; ++i) {
            const int gr = row0 + rql + 8 * i;
            *(float4*)(ep + i * 4) = *(const float4*)&init_state[gr * HH + col0 + clo];
        }
    }
    grid_barrier(1u);

    #pragma unroll 1
    for (int t = 0; t < TT; ++t) {
        const float* Ot = out + (size_t)t * (BB * HH);
        float*       On = out + (size_t)(t + 1) * (BB * HH);

        // Group0: park epilogue operands (cold-DRAM noise + input) in private SMEM
        // slots now, so their latency overlaps the whole GEMM instead of the tail.
        // Own-thread write/read -> program order, no sync needed.
        if (group == 0) {
            float* ep = &sEpi[s * EPI_STRIDE];
            #pragma unroll
            for (int i = 0; i < 4; ++i) {
                const int gr = row0 + rql + 8 * i;
                const float4 nzv = *(const float4*)&noise[((size_t)t * BB + gr) * HH + col0 + clo];
                const float2 ivv = *(const float2*)&inp[((size_t)t * BB + gr) * 2];
                *(float4*)(ep + 16 + i * 4) = nzv;
                *(float2*)(ep + 32 + i * 2) = ivv;
            }
        }

        // Stage chunk 0 (two quads per thread)
        {
            float4 v0 = *(const float4*)&Ot[(row0 + l_r) * HH + l_q * 4];
            float4 v1 = *(const float4*)&Ot[(row0 + l_r) * HH + l_q * 4 + 64];
            v0.x = fmaxf(v0.x, 0.f); v0.y = fmaxf(v0.y, 0.f); v0.z = fmaxf(v0.z, 0.f); v0.w = fmaxf(v0.w, 0.f);
            v1.x = fmaxf(v1.x, 0.f); v1.y = fmaxf(v1.y, 0.f); v1.z = fmaxf(v1.z, 0.f); v1.w = fmaxf(v1.w, 0.f);
            *(float4*)&sA[l_r * ASTRIDE + l_q * 4]      = v0;
            *(float4*)&sA[l_r * ASTRIDE + l_q * 4 + 64] = v1;
        }
        __syncthreads();

        unsigned long long acc[4][4];
        #pragma unroll
        for (int i = 0; i < 4; ++i)
            #pragma unroll
            for (int j = 0; j < 4; ++j) acc[i][j] = 0ull;

        #pragma unroll 1
        for (int ck = 0; ck < NCHUNK; ++ck) {
            // Prefetch next chunk (writes target the buffer whose readers finished
            // at the sync that ended chunk ck-1, so STS may be scheduled anywhere)
            float4 v0, v1;
            const int nb = (ck + 1) & 1;
            if (ck < NCHUNK - 1) {
                const int kb = (ck + 1) * CK;
                v0 = *(const float4*)&Ot[(row0 + l_r) * HH + kb + l_q * 4];
                v1 = *(const float4*)&Ot[(row0 + l_r) * HH + kb + l_q * 4 + 64];
            }

            const float* aB = &sA[(ck & 1) * ABUF];
            const int jloc  = group * PAIRS_PER_GROUP;           // pair idx within chunk
            const int jglob = ck * PAIRS_PER_CHUNK + jloc;       // global pair idx
            #pragma unroll
            for (int jj = 0; jj < PAIRS_PER_GROUP; ++jj) {
                const int jo2 = (jloc + jj) * 2;
                // a pairs (k even, k odd) for 4 strided rows
                const unsigned long long a0 = *(const unsigned long long*)(aB + (rql +  0) * ASTRIDE + jo2);
                const unsigned long long a1 = *(const unsigned long long*)(aB + (rql +  8) * ASTRIDE + jo2);
                const unsigned long long a2 = *(const unsigned long long*)(aB + (rql + 16) * ASTRIDE + jo2);
                const unsigned long long a3 = *(const unsigned long long*)(aB + (rql + 24) * ASTRIDE + jo2);
                // W k-pairs for 4 cols
                const float* wj = sW + (size_t)(jglob + jj) * 64 + cql * 8;
                const ulonglong2 w01 = *(const ulonglong2*)(wj);
                const ulonglong2 w23 = *(const ulonglong2*)(wj + 4);
                FMA2(acc[0][0], a0, w01.x); FMA2(acc[0][1], a0, w01.y);
                FMA2(acc[0][2], a0, w23.x); FMA2(acc[0][3], a0, w23.y);
                FMA2(acc[1][0], a1, w01.x); FMA2(acc[1][1], a1, w01.y);
                FMA2(acc[1][2], a1, w23.x); FMA2(acc[1][3], a1, w23.y);
                FMA2(acc[2][0], a2, w01.x); FMA2(acc[2][1], a2, w01.y);
                FMA2(acc[2][2], a2, w23.x); FMA2(acc[2][3], a2, w23.y);
                FMA2(acc[3][0], a3, w01.x); FMA2(acc[3][1], a3, w01.y);
                FMA2(acc[3][2], a3, w23.x); FMA2(acc[3][3], a3, w23.y);
            }

            if (ck < NCHUNK - 1) {
                v0.x = fmaxf(v0.x, 0.f); v0.y = fmaxf(v0.y, 0.f); v0.z = fmaxf(v0.z, 0.f); v0.w = fmaxf(v0.w, 0.f);
                v1.x = fmaxf(v1.x, 0.f); v1.y = fmaxf(v1.y, 0.f); v1.z = fmaxf(v1.z, 0.f); v1.w = fmaxf(v1.w, 0.f);
                *(float4*)&sA[nb * ABUF + l_r * ASTRIDE + l_q * 4]      = v0;
                *(float4*)&sA[nb * ABUF + l_r * ASTRIDE + l_q * 4 + 64] = v1;
                __syncthreads();
            }
        }

        // Pair-sum: even-k + odd-k partials
        float c_[4][4];
        #pragma unroll
        for (int i = 0; i < 4; ++i)
            #pragma unroll
            for (int j = 0; j < 4; ++j) {
                unsigned lo, hi;
                asm("mov.b64 {%0, %1}, %2;" : "=r"(lo), "=r"(hi) : "l"(acc[i][j]));
                c_[i][j] = __uint_as_float(lo) + __uint_as_float(hi);
            }

        // Groups 1-7: store partial tiles.
        if (group != 0) {
            float* dst = &sScr[(group - 1) * SCR_GROUP + s * SCR_STRIDE];
            #pragma unroll
            for (int i = 0; i < 4; ++i)
                *(float4*)(dst + i * 4) = make_float4(c_[i][0], c_[i][1], c_[i][2], c_[i][3]);
        }
        __syncthreads();

        if (group == 0) {
            // Reduce the 7 partial tiles
            #pragma unroll 1
            for (int g = 1; g < NGROUP; ++g) {
                const float* src = &sScr[(g - 1) * SCR_GROUP + s * SCR_STRIDE];
                #pragma unroll
                for (int i = 0; i < 4; ++i) {
                    const float4 p = *(const float4*)(src + i * 4);
                    c_[i][0] += p.x; c_[i][1] += p.y; c_[i][2] += p.z; c_[i][3] += p.w;
                }
            }

            const float wa0 = sWih[clo],      wa1 = sWih[clo + 1],      wa2 = sWih[clo + 2],      wa3 = sWih[clo + 3];
            const float wb0 = sWih[32 + clo], wb1 = sWih[32 + clo + 1], wb2 = sWih[32 + clo + 2], wb3 = sWih[32 + clo + 3];
            const float b0  = sBias[clo],     b1  = sBias[clo + 1],     b2  = sBias[clo + 2],     b3  = sBias[clo + 3];

            float* ep = &sEpi[s * EPI_STRIDE];
            #pragma unroll
            for (int i = 0; i < 4; ++i) {
                const int gr = row0 + rql + 8 * i;
                const float4 old4 = *(const float4*)(ep + i * 4);        // carried state (SMEM)
                const float4 nz4  = *(const float4*)(ep + 16 + i * 4);   // parked at step start
                const float2 iv2  = *(const float2*)(ep + 32 + i * 2);
                float4 res;
                res.x = 0.8f * old4.x + 0.2f * (c_[i][0] + iv2.x * wa0 + iv2.y * wb0 + b0 + SIGMA_REC * nz4.x);
                res.y = 0.8f * old4.y + 0.2f * (c_[i][1] + iv2.x * wa1 + iv2.y * wb1 + b1 + SIGMA_REC * nz4.y);
                res.z = 0.8f * old4.z + 0.2f * (c_[i][2] + iv2.x * wa2 + iv2.y * wb2 + b2 + SIGMA_REC * nz4.z);
                res.w = 0.8f * old4.w + 0.2f * (c_[i][3] + iv2.x * wa3 + iv2.y * wb3 + b3 + SIGMA_REC * nz4.w);
                *(float4*)(ep + i * 4) = res;                            // carry for next step
                *(float4*)&On[gr * HH + col0 + clo] = res;
            }
        }

        grid_barrier((unsigned)(t + 2));
    }
}

extern "C" void kernel_launch(void* const* d_in, const int* in_sizes, int n_in,
                              void* d_out, int out_size) {
    const float* inp   = (const float*)d_in[0];  // [512,128,2]
    const float* inis  = (const float*)d_in[1];  // [128,1024]
    const float* noise = (const float*)d_in[2];  // [512,128,1024]
    const float* wih   = (const float*)d_in[3];  // [2,1024]
    const float* whh   = (const float*)d_in[4];  // [1024,1024]
    const float* bias  = (const float*)d_in[5];  // [1,1024]
    float* out = (float*)d_out;                  // [513,128,1024]

    cudaFuncSetAttribute(rnn_persistent_kernel,
                         cudaFuncAttributeMaxDynamicSharedMemorySize, SMEM_BYTES);

    rnn_init_kernel<<<1, 128>>>();
    rnn_persistent_kernel<<<NCTA, NTHREADS, SMEM_BYTES>>>(inp, inis, noise, wih, whh, bias, out);
}

// round 15
// speedup vs baseline: 1.0783x; 1.0275x over previous
#include <cuda_runtime.h>
#include <cstdint>

// Problem constants
#define TT 512
#define BB 128
#define HH 1024
#define SIGMA_REC 0.15811388300841897f   // sqrt(2/0.2)*0.05

// Grid / threads  (R15: 2 CTAs/SM, 16-col strips)
#define NCTA 256          // 4 row-blocks x 64 col-blocks
#define NTHREADS 256      // 8 k-split groups x 32 threads
#define NGROUP 8
#define CK 64             // k per staged chunk
#define NCHUNK (HH / CK)  // 16
#define PAIRS_PER_CHUNK 32
#define PAIRS_PER_GROUP 4

// SMEM layout (floats)
#define NC 16                        // cols per CTA
#define ASTRIDE 68                   // 64 k + 4 pad
#define ABUF (32 * ASTRIDE)          // 2176
#define W_FLOATS (HH * NC)           // 16384, k-pair-interleaved: (k>>1)*32 + c*2 + (k&1)
#define A_OFF W_FLOATS               // 16384
#define SCR_OFF (A_OFF + 2 * ABUF)   // 20736
#define SCR_STRIDE 20
#define SCR_GROUP (32 * SCR_STRIDE)  // 640
#define EPI_OFF (SCR_OFF + 7 * SCR_GROUP)  // 25216
#define EPI_STRIDE 44                // old[16] nz[16] iv[8] + pad
#define WIH_OFF (EPI_OFF + 32 * EPI_STRIDE) // 26624
#define BIAS_OFF (WIH_OFF + 32)             // 26656
#define SMEM_FLOATS (BIAS_OFF + 16)         // 26672
#define SMEM_BYTES (SMEM_FLOATS * 4)        // 106688 B -> 2 CTAs = 213376 < 228KB

#define FMA2(acc, a, w) asm("fma.rn.f32x2 %0, %1, %2, %0;" : "+l"(acc) : "l"(a), "l"(w))

__device__ unsigned g_flags[NCTA];

__global__ void rnn_init_kernel() {
    if (threadIdx.x < NCTA) g_flags[threadIdx.x] = 0u;
}

__device__ __forceinline__ void st_rel(unsigned* p, unsigned v) {
    asm volatile("st.global.release.gpu.u32 [%0], %1;" :: "l"(p), "r"(v) : "memory");
}
__device__ __forceinline__ unsigned ld_acq(const unsigned* p) {
    unsigned v;
    asm volatile("ld.global.acquire.gpu.u32 %0, [%1];" : "=r"(v) : "l"(p) : "memory");
    return v;
}

// All-CTA barrier: per-CTA release flag + 256 threads poll the 256 flags.
// 256 CTAs, 2/SM occupancy cap, 148 SMs (capacity 296) -> single wave, co-resident.
__device__ __forceinline__ void grid_barrier(unsigned epoch) {
    __syncthreads();
    if (threadIdx.x == 0) st_rel(&g_flags[blockIdx.x], epoch);
    const unsigned idx = threadIdx.x & (NCTA - 1);
    while (ld_acq(&g_flags[idx]) < epoch) { }
    __syncthreads();
}

__global__ void __launch_bounds__(NTHREADS, 2)
rnn_persistent_kernel(const float* __restrict__ inp,
                      const float* __restrict__ init_state,
                      const float* __restrict__ noise,
                      const float* __restrict__ wih,
                      const float* __restrict__ whh,
                      const float* __restrict__ bias,
                      float* __restrict__ out)
{
    extern __shared__ float sm[];
    float* sW    = sm;              // [512 j][16 c][2 parity]
    float* sA    = sm + A_OFF;      // [2][32 r][68]
    float* sScr  = sm + SCR_OFF;    // [7 g][32 s][20]
    float* sEpi  = sm + EPI_OFF;    // [32 s][44]
    float* sWih  = sm + WIH_OFF;    // [2][16]
    float* sBias = sm + BIAS_OFF;   // [16]

    const int tid  = threadIdx.x;
    const int cta  = blockIdx.x;
    const int row0 = (cta >> 6) * 32;   // 4 row blocks
    const int col0 = (cta & 63) * NC;   // 64 col blocks of 16

    // One-time: stage W strip k-pair-interleaved
    for (int idx = tid; idx < W_FLOATS; idx += NTHREADS) {
        const int k = idx >> 4, c = idx & 15;
        sW[(k >> 1) * 32 + c * 2 + (k & 1)] = whh[k * HH + col0 + c];
    }
    if (tid < 16) {
        sWih[tid]      = wih[col0 + tid];
        sWih[16 + tid] = wih[HH + col0 + tid];
        sBias[tid]     = bias[col0 + tid];
    }

    // K-split groups: group g handles pairs [g*4, g*4+4) of every 32-pair chunk.
    const int group = tid >> 5;         // 0..7
    const int s     = tid & 31;
    const int cql   = s >> 3;           // 0..3 -> cols cql*4..+3
    const int rql   = s & 7;            // rows {rql, rql+8, rql+16, rql+24}
    const int clo   = cql * 4;

    // Staging mapping: thread stores two relu'd float4 (rows l_r, l_r+16; quad l_q)
    const int l_r = tid >> 4;           // 0..15
    const int l_q = tid & 15;           // 0..15

    // out[0] = initial_state (32x16 tile = 128 float4); group0 seeds old-state slots.
    if (tid < 128) {
        const int r = tid >> 2, c4 = (tid & 3) * 4;
        const float4 v = *(const float4*)&init_state[(row0 + r) * HH + col0 + c4];
        *(float4*)&out[(row0 + r) * HH + col0 + c4] = v;
    }
    if (group == 0) {
        float* ep = &sEpi[s * EPI_STRIDE];
        #pragma unroll
        for (int i = 0; i < 4; ++i) {
            const int gr = row0 + rql + 8 * i;
            *(float4*)(ep + i * 4) = *(const float4*)&init_state[gr * HH + col0 + clo];
        }
    }
    grid_barrier(1u);

    #pragma unroll 1
    for (int t = 0; t < TT; ++t) {
        const float* Ot = out + (size_t)t * (BB * HH);
        float*       On = out + (size_t)(t + 1) * (BB * HH);

        // Group0: park epilogue operands (cold-DRAM noise + input) in private SMEM
        // slots now; latency overlaps the whole GEMM. Own-thread order, no sync.
        if (group == 0) {
            float* ep = &sEpi[s * EPI_STRIDE];
            #pragma unroll
            for (int i = 0; i < 4; ++i) {
                const int gr = row0 + rql + 8 * i;
                const float4 nzv = *(const float4*)&noise[((size_t)t * BB + gr) * HH + col0 + clo];
                const float2 ivv = *(const float2*)&inp[((size_t)t * BB + gr) * 2];
                *(float4*)(ep + 16 + i * 4) = nzv;
                *(float2*)(ep + 32 + i * 2) = ivv;
            }
        }

        // Stage chunk 0 (rows l_r and l_r+16)
        {
            float4 v0 = *(const float4*)&Ot[(row0 + l_r) * HH + l_q * 4];
            float4 v1 = *(const float4*)&Ot[(row0 + l_r + 16) * HH + l_q * 4];
            v0.x = fmaxf(v0.x, 0.f); v0.y = fmaxf(v0.y, 0.f); v0.z = fmaxf(v0.z, 0.f); v0.w = fmaxf(v0.w, 0.f);
            v1.x = fmaxf(v1.x, 0.f); v1.y = fmaxf(v1.y, 0.f); v1.z = fmaxf(v1.z, 0.f); v1.w = fmaxf(v1.w, 0.f);
            *(float4*)&sA[l_r * ASTRIDE + l_q * 4]        = v0;
            *(float4*)&sA[(l_r + 16) * ASTRIDE + l_q * 4] = v1;
        }
        __syncthreads();

        unsigned long long acc[4][4];
        #pragma unroll
        for (int i = 0; i < 4; ++i)
            #pragma unroll
            for (int j = 0; j < 4; ++j) acc[i][j] = 0ull;

        #pragma unroll 1
        for (int ck = 0; ck < NCHUNK; ++ck) {
            float4 v0, v1;
            const int nb = (ck + 1) & 1;
            if (ck < NCHUNK - 1) {
                const int kb = (ck + 1) * CK;
                v0 = *(const float4*)&Ot[(row0 + l_r) * HH + kb + l_q * 4];
                v1 = *(const float4*)&Ot[(row0 + l_r + 16) * HH + kb + l_q * 4];
            }

            const float* aB = &sA[(ck & 1) * ABUF];
            const int jloc  = group * PAIRS_PER_GROUP;
            const int jglob = ck * PAIRS_PER_CHUNK + jloc;
            #pragma unroll
            for (int jj = 0; jj < PAIRS_PER_GROUP; ++jj) {
                const int jo2 = (jloc + jj) * 2;
                const unsigned long long a0 = *(const unsigned long long*)(aB + (rql +  0) * ASTRIDE + jo2);
                const unsigned long long a1 = *(const unsigned long long*)(aB + (rql +  8) * ASTRIDE + jo2);
                const unsigned long long a2 = *(const unsigned long long*)(aB + (rql + 16) * ASTRIDE + jo2);
                const unsigned long long a3 = *(const unsigned long long*)(aB + (rql + 24) * ASTRIDE + jo2);
                const float* wj = sW + (size_t)(jglob + jj) * 32 + cql * 8;
                const ulonglong2 w01 = *(const ulonglong2*)(wj);
                const ulonglong2 w23 = *(const ulonglong2*)(wj + 4);
                FMA2(acc[0][0], a0, w01.x); FMA2(acc[0][1], a0, w01.y);
                FMA2(acc[0][2], a0, w23.x); FMA2(acc[0][3], a0, w23.y);
                FMA2(acc[1][0], a1, w01.x); FMA2(acc[1][1], a1, w01.y);
                FMA2(acc[1][2], a1, w23.x); FMA2(acc[1][3], a1, w23.y);
                FMA2(acc[2][0], a2, w01.x); FMA2(acc[2][1], a2, w01.y);
                FMA2(acc[2][2], a2, w23.x); FMA2(acc[2][3], a2, w23.y);
                FMA2(acc[3][0], a3, w01.x); FMA2(acc[3][1], a3, w01.y);
                FMA2(acc[3][2], a3, w23.x); FMA2(acc[3][3], a3, w23.y);
            }

            if (ck < NCHUNK - 1) {
                v0.x = fmaxf(v0.x, 0.f); v0.y = fmaxf(v0.y, 0.f); v0.z = fmaxf(v0.z, 0.f); v0.w = fmaxf(v0.w, 0.f);
                v1.x = fmaxf(v1.x, 0.f); v1.y = fmaxf(v1.y, 0.f); v1.z = fmaxf(v1.z, 0.f); v1.w = fmaxf(v1.w, 0.f);
                *(float4*)&sA[nb * ABUF + l_r * ASTRIDE + l_q * 4]        = v0;
                *(float4*)&sA[nb * ABUF + (l_r + 16) * ASTRIDE + l_q * 4] = v1;
                __syncthreads();
            }
        }

        // Pair-sum: even-k + odd-k partials
        float c_[4][4];
        #pragma unroll
        for (int i = 0; i < 4; ++i)
            #pragma unroll
            for (int j = 0; j < 4; ++j) {
                unsigned lo, hi;
                asm("mov.b64 {%0, %1}, %2;" : "=r"(lo), "=r"(hi) : "l"(acc[i][j]));
                c_[i][j] = __uint_as_float(lo) + __uint_as_float(hi);
            }

        if (group != 0) {
            float* dst = &sScr[(group - 1) * SCR_GROUP + s * SCR_STRIDE];
            #pragma unroll
            for (int i = 0; i < 4; ++i)
                *(float4*)(dst + i * 4) = make_float4(c_[i][0], c_[i][1], c_[i][2], c_[i][3]);
        }
        __syncthreads();

        if (group == 0) {
            #pragma unroll 1
            for (int g = 1; g < NGROUP; ++g) {
                const float* src = &sScr[(g - 1) * SCR_GROUP + s * SCR_STRIDE];
                #pragma unroll
                for (int i = 0; i < 4; ++i) {
                    const float4 p = *(const float4*)(src + i * 4);
                    c_[i][0] += p.x; c_[i][1] += p.y; c_[i][2] += p.z; c_[i][3] += p.w;
                }
            }

            const float wa0 = sWih[clo],      wa1 = sWih[clo + 1],      wa2 = sWih[clo + 2],      wa3 = sWih[clo + 3];
            const float wb0 = sWih[16 + clo], wb1 = sWih[16 + clo + 1], wb2 = sWih[16 + clo + 2], wb3 = sWih[16 + clo + 3];
            const float b0  = sBias[clo],     b1  = sBias[clo + 1],     b2  = sBias[clo + 2],     b3  = sBias[clo + 3];

            float* ep = &sEpi[s * EPI_STRIDE];
            #pragma unroll
            for (int i = 0; i < 4; ++i) {
                const int gr = row0 + rql + 8 * i;
                const float4 old4 = *(const float4*)(ep + i * 4);
                const float4 nz4  = *(const float4*)(ep + 16 + i * 4);
                const float2 iv2  = *(const float2*)(ep + 32 + i * 2);
                float4 res;
                res.x = 0.8f * old4.x + 0.2f * (c_[i][0] + iv2.x * wa0 + iv2.y * wb0 + b0 + SIGMA_REC * nz4.x);
                res.y = 0.8f * old4.y + 0.2f * (c_[i][1] + iv2.x * wa1 + iv2.y * wb1 + b1 + SIGMA_REC * nz4.y);
                res.z = 0.8f * old4.z + 0.2f * (c_[i][2] + iv2.x * wa2 + iv2.y * wb2 + b2 + SIGMA_REC * nz4.z);
                res.w = 0.8f * old4.w + 0.2f * (c_[i][3] + iv2.x * wa3 + iv2.y * wb3 + b3 + SIGMA_REC * nz4.w);
                *(float4*)(ep + i * 4) = res;
                *(float4*)&On[gr * HH + col0 + clo] = res;
            }
        }

        grid_barrier((unsigned)(t + 2));
    }
}

extern "C" void kernel_launch(void* const* d_in, const int* in_sizes, int n_in,
                              void* d_out, int out_size) {
    const float* inp   = (const float*)d_in[0];  // [512,128,2]
    const float* inis  = (const float*)d_in[1];  // [128,1024]
    const float* noise = (const float*)d_in[2];  // [512,128,1024]
    const float* wih   = (const float*)d_in[3];  // [2,1024]
    const float* whh   = (const float*)d_in[4];  // [1024,1024]
    const float* bias  = (const float*)d_in[5];  // [1,1024]
    float* out = (float*)d_out;                  // [513,128,1024]

    cudaFuncSetAttribute(rnn_persistent_kernel,
                         cudaFuncAttributeMaxDynamicSharedMemorySize, SMEM_BYTES);

    rnn_init_kernel<<<1, NCTA>>>();
    rnn_persistent_kernel<<<NCTA, NTHREADS, SMEM_BYTES>>>(inp, inis, noise, wih, whh, bias, out);
}